// round 13
// baseline (speedup 1.0000x reference)
#include <cuda_runtime.h>
#include <cuda_bf16.h>
#include <cstdint>
#include <math.h>

// ---------------------------------------------------------------------------
// GCN + TopK pooling stack (3 layers), B=128 graphs, N=1024 nodes, H=128.
// GEMM: mma.sync m16n8k8 tf32 3-term split; A double-buffered in smem,
// B fragments streamed directly from L2. Single-kernel lookback scan.
// Warp-shfl bitonic topk.
// ---------------------------------------------------------------------------

#define Bg   128
#define Npg  1024
#define Hd   128
#define NN1  (Bg*Npg)        // 131072
#define NN2  (Bg*512)        // 65536
#define NN3  (Bg*256)        // 32768
#define EMAX 1048576

// ------------------------- device scratch (no allocs) ----------------------
__device__ __align__(128) float g_h [NN1*Hd];
__device__ __align__(128) float g_cv[NN1*Hd];
__device__ __align__(128) float g_xs1[NN2*Hd];
__device__ __align__(128) float g_xs2[NN3*Hd];
__device__ __align__(128) float g_xs3[(Bg*128)*Hd];
__device__ __align__(16) float g_bf[3*32768];   // W frags {hi0,hi1,lo0,lo1}
__device__ float g_dinv[NN1];
__device__ float g_sc[NN1];
__device__ int   g_newid[NN1];
__device__ int   g_cnt[NN1];
__device__ int   g_start[NN1];
__device__ int   g_cursor[NN1];
__device__ unsigned long long g_tstate[3*128];   // lookback scan states
__device__ int   g_src[EMAX];
__device__ int   g_r0[EMAX], g_c0[EMAX];
__device__ int   g_r1[EMAX], g_c1[EMAX];
__device__ int   g_nE[2];
__device__ float g_pinv[3];

// --------------------------- helpers ----------------------------------------
__device__ __forceinline__ float tf32r(float v) {
    float h;
    asm("cvt.rna.tf32.f32 %0, %1;" : "=f"(h) : "f"(v));
    return h;
}

__device__ __forceinline__ void mma8(float* c, const float4 a, const float2 b) {
    asm volatile(
        "mma.sync.aligned.m16n8k8.row.col.f32.tf32.tf32.f32 "
        "{%0,%1,%2,%3}, {%4,%5,%6,%7}, {%8,%9}, {%0,%1,%2,%3};"
        : "+f"(c[0]), "+f"(c[1]), "+f"(c[2]), "+f"(c[3])
        : "r"(__float_as_uint(a.x)), "r"(__float_as_uint(a.y)),
          "r"(__float_as_uint(a.z)), "r"(__float_as_uint(a.w)),
          "r"(__float_as_uint(b.x)), "r"(__float_as_uint(b.y)));
}

// ---- W frag split + pnorm + replay zero-init, one kernel (grid 779) --------
__global__ void wsplit_k(const float* __restrict__ W1, const float* __restrict__ W2,
                         const float* __restrict__ W3,
                         const float* __restrict__ p1, const float* __restrict__ p2,
                         const float* __restrict__ p3,
                         float* __restrict__ bf, int* __restrict__ cnt,
                         int* __restrict__ cursor, unsigned long long* __restrict__ ts) {
    __shared__ float sp[128];
    int bid = blockIdx.x, t = threadIdx.x;
    if (bid < 768) {
        int layer = bid >> 8;
        int idx = (bid & 255) * 128 + t;          // 0..32767
        const float* W = (layer == 0) ? W1 : (layer == 1) ? W2 : W3;
        int j  = idx & 3;
        int l  = (idx >> 2) & 31;
        int ks = (idx >> 7) & 3;
        int nt = (idx >> 9) & 15;
        int kc = idx >> 13;
        int k = kc * 32 + ks * 8 + (l & 3) + ((j & 1) << 2);
        int n = nt * 8 + (l >> 2);
        float v = W[k * 128 + n];
        float h = tf32r(v);
        bf[layer * 32768 + idx] = (j < 2) ? h : (v - h);
    } else if (bid < 771) {
        const float* p = (bid == 768) ? p1 : (bid == 769) ? p2 : p3;
        float v = p[t];
        sp[t] = v * v;
        __syncthreads();
        for (int o = 64; o > 0; o >>= 1) {
            if (t < o) sp[t] += sp[t + o];
            __syncthreads();
        }
        if (t == 0) g_pinv[bid - 768] = rsqrtf(sp[0]);
    } else {
        int z = (bid - 771) * 128 + t;            // 0..1023
        int4 z4 = make_int4(0, 0, 0, 0);
        for (int q = z; q < NN1 / 4; q += 1024) {
            ((int4*)cnt)[q] = z4;
            ((int4*)cursor)[q] = z4;
        }
        if (z < 384) ts[z] = 0ull;
    }
}

// --------------------------- mma.sync GEMM ----------------------------------
// A double-buffered in smem (stage kc+1 while computing kc); B fragments
// streamed directly from global (L2-resident, shared across all CTAs).
__device__ __forceinline__ void stageA(const float* __restrict__ X, long row0,
                                       int kc, float* __restrict__ dst, int tid) {
#pragma unroll
    for (int i = 0; i < 4; i++) {
        int f = tid + i * 256;
        int fl = f & 31, ks = (f >> 5) & 3, mt = f >> 7;
        long row = row0 + mt * 16 + (fl >> 2);
        int k = kc * 32 + ks * 8 + (fl & 3);
        float v0 = X[row * 128 + k];
        float v1 = X[(row + 8) * 128 + k];
        float v2 = X[row * 128 + k + 4];
        float v3 = X[(row + 8) * 128 + k + 4];
        float h0 = tf32r(v0), h1 = tf32r(v1), h2 = tf32r(v2), h3 = tf32r(v3);
        int o = f * 8;
        *(float4*)&dst[o]     = make_float4(h0, h1, h2, h3);
        *(float4*)&dst[o + 4] = make_float4(v0 - h0, v1 - h1, v2 - h2, v3 - h3);
    }
}

__global__ void __launch_bounds__(256, 2)
gemm_mma(const float* __restrict__ X, const float* __restrict__ Bf,
         const int* __restrict__ cnt, float* __restrict__ Out)
{
    __shared__ float sA[2][8192];    // [buf][mt][ks][lane][8] 32KB each
    const int tid = threadIdx.x;
    const int w = tid >> 5, l = tid & 31;
    const long row0 = (long)blockIdx.x * 128;

    float acc[16][4];
#pragma unroll
    for (int nt = 0; nt < 16; nt++)
#pragma unroll
        for (int j = 0; j < 4; j++) acc[nt][j] = 0.f;

    stageA(X, row0, 0, sA[0], tid);
    __syncthreads();

    for (int kc = 0; kc < 4; kc++) {
        if (kc < 3) stageA(X, row0, kc + 1, sA[(kc + 1) & 1], tid);
        const float* sAc = sA[kc & 1];
        const float4* bp = (const float4*)(Bf + kc * 8192);  // [nt*128+ks*32+l]
#pragma unroll
        for (int ks = 0; ks < 4; ks++) {
            const float4* ap = (const float4*)&sAc[((w * 4 + ks) * 32 + l) * 8];
            float4 ah = ap[0];
            float4 al = ap[1];
            const float4* bks = bp + ks * 32 + l;
#pragma unroll
            for (int nt = 0; nt < 16; nt++) {
                float4 bq = __ldg(bks + nt * 128);
                float2 bh = make_float2(bq.x, bq.y);
                float2 bl = make_float2(bq.z, bq.w);
                mma8(acc[nt], ah, bh);
                mma8(acc[nt], ah, bl);
                mma8(acc[nt], al, bh);
            }
        }
        __syncthreads();
    }

    int r0 = (int)row0 + w * 16 + (l >> 2);
    float dv0 = rsqrtf((float)__ldg(&cnt[r0]) + 1.0f);
    float dv1 = rsqrtf((float)__ldg(&cnt[r0 + 8]) + 1.0f);
#pragma unroll
    for (int nt = 0; nt < 16; nt++) {
        int col = nt * 8 + (l & 3) * 2;
        *(float2*)&Out[(long)r0 * 128 + col] =
            make_float2(acc[nt][0] * dv0, acc[nt][1] * dv0);
        *(float2*)&Out[(long)(r0 + 8) * 128 + col] =
            make_float2(acc[nt][2] * dv1, acc[nt][3] * dv1);
    }
}

// --------------------------- hist -------------------------------------------
__global__ void hist_k(const int* __restrict__ col, int* __restrict__ cnt, int nE) {
    int i = blockIdx.x * blockDim.x + threadIdx.x;
    if (i < nE) atomicAdd(&cnt[col[i]], 1);
}

// ---- single-kernel exclusive scan (decoupled lookback; grid <= 128) --------
__global__ void scan_k(const int* __restrict__ cnt, int* __restrict__ start,
                       float* __restrict__ dinv, unsigned long long* __restrict__ st)
{
    __shared__ int s[1024];
    __shared__ int s_prefix;
    int t = threadIdx.x, b = blockIdx.x;
    int i = b * 1024 + t;
    int v = cnt[i];
    s[t] = v;
    __syncthreads();
    for (int o = 1; o < 1024; o <<= 1) {
        int add = (t >= o) ? s[t - o] : 0;
        __syncthreads();
        s[t] += add;
        __syncthreads();
    }
    if (t == 0) {
        int total = s[1023];
        atomicExch(&st[b], (((unsigned long long)total) << 2) | 1ull);  // PARTIAL
        int ex = 0;
        for (int j = b - 1; j >= 0; j--) {
            unsigned long long f;
            do { f = atomicAdd(&st[j], 0ull); } while ((f & 3ull) == 0ull);
            ex += (int)(f >> 2);
            if ((f & 3ull) == 2ull) break;       // PREFIX: inclusive, stop
        }
        atomicExch(&st[b], (((unsigned long long)(ex + total)) << 2) | 2ull);
        s_prefix = ex;
    }
    __syncthreads();
    start[i] = s[t] - v + s_prefix;
    dinv[i] = rsqrtf((float)v + 1.0f);
}

__global__ void fill_k(const int* __restrict__ row, const int* __restrict__ col,
                       const int* __restrict__ start, int* __restrict__ cursor,
                       int* __restrict__ src, const int* __restrict__ boundPtr,
                       int maxE) {
    int i = blockIdx.x * blockDim.x + threadIdx.x;
    int bound = boundPtr ? __ldg(boundPtr) : maxE;
    if (i >= bound) return;
    int c = col[i];
    int p = atomicAdd(&cursor[c], 1);
    src[start[c] + p] = row[i];
}

// ---- gather (h is dinv-prescaled) + self + bias + relu + score, fused ------
__global__ void gather_k(const float* __restrict__ h, const int* __restrict__ start,
                         const int* __restrict__ cnt, const int* __restrict__ src,
                         const float* __restrict__ dinv, const float* __restrict__ b,
                         const float* __restrict__ p, const float* __restrict__ pinv,
                         float* __restrict__ out, float* __restrict__ score, int n) {
    int w = (blockIdx.x * blockDim.x + threadIdx.x) >> 5;
    if (w >= n) return;
    int lane = threadIdx.x & 31;
    float dc = dinv[w];
    int s0 = start[w], d = cnt[w];
    float4 acc = ((const float4*)(h + (long)w * Hd))[lane];

    int e = 0;
    for (; e + 4 <= d; e += 4) {
        int r0 = __ldg(&src[s0 + e]);
        int r1 = __ldg(&src[s0 + e + 1]);
        int r2 = __ldg(&src[s0 + e + 2]);
        int r3 = __ldg(&src[s0 + e + 3]);
        float4 v0 = ((const float4*)(h + (long)r0 * Hd))[lane];
        float4 v1 = ((const float4*)(h + (long)r1 * Hd))[lane];
        float4 v2 = ((const float4*)(h + (long)r2 * Hd))[lane];
        float4 v3 = ((const float4*)(h + (long)r3 * Hd))[lane];
        acc.x += v0.x + v1.x + v2.x + v3.x;
        acc.y += v0.y + v1.y + v2.y + v3.y;
        acc.z += v0.z + v1.z + v2.z + v3.z;
        acc.w += v0.w + v1.w + v2.w + v3.w;
    }
    for (; e < d; e++) {
        int r = __ldg(&src[s0 + e]);
        float4 v = ((const float4*)(h + (long)r * Hd))[lane];
        acc.x += v.x; acc.y += v.y; acc.z += v.z; acc.w += v.w;
    }

    float4 bv = ((const float4*)b)[lane];
    acc.x = fmaxf(fmaf(acc.x, dc, bv.x), 0.f);
    acc.y = fmaxf(fmaf(acc.y, dc, bv.y), 0.f);
    acc.z = fmaxf(fmaf(acc.z, dc, bv.z), 0.f);
    acc.w = fmaxf(fmaf(acc.w, dc, bv.w), 0.f);
    ((float4*)(out + (long)w * Hd))[lane] = acc;

    float4 pv = ((const float4*)p)[lane];
    float s = acc.x*pv.x + acc.y*pv.y + acc.z*pv.z + acc.w*pv.w;
#pragma unroll
    for (int o = 16; o; o >>= 1) s += __shfl_xor_sync(0xffffffffu, s, o);
    if (lane == 0) score[w] = s * __ldg(pinv);
}

// ------- top-k (matches jax.lax.top_k) + readout + next-layer zeroing -------
__global__ void topk_k(const float* __restrict__ x, const float* __restrict__ score,
                       float* __restrict__ xs, int* __restrict__ newid,
                       int n_per, int k,
                       float* __restrict__ out, int addFlag,
                       int* __restrict__ cnt_next, int* __restrict__ cursor_next,
                       int* __restrict__ counter_next, int n_next) {
    __shared__ unsigned long long keys[1024];
    __shared__ float tv_s[512];
    __shared__ int   sel_s[512];
    int g = blockIdx.x, t = threadIdx.x;
    int base = g * n_per;
    int gid = base + t;

    if (n_next > 0) {
        if (gid < n_next) { cnt_next[gid] = 0; cursor_next[gid] = 0; }
        if (gid == 0) *counter_next = 0;
    }

    newid[gid] = -1;
    float s = score[gid];
    unsigned int fb = __float_as_uint(s);
    unsigned int mp = (fb & 0x80000000u) ? ~fb : (fb | 0x80000000u);
    unsigned long long key = ((unsigned long long)(~mp) << 32) | (unsigned int)t;

#pragma unroll
    for (int kk = 2; kk <= 32; kk <<= 1) {
#pragma unroll
        for (int j = kk >> 1; j >= 1; j >>= 1) {
            unsigned long long part = __shfl_xor_sync(0xffffffffu, key, j);
            bool takeMin = (((t & j) == 0) == ((t & kk) == 0));
            key = takeMin ? (key < part ? key : part) : (key > part ? key : part);
        }
    }
    keys[t] = key;
    __syncthreads();

    for (int kk = 64; kk <= n_per; kk <<= 1) {
        for (int j = kk >> 1; j >= 32; j >>= 1) {
            int ixj = t ^ j;
            if (ixj > t) {
                bool up = ((t & kk) == 0);
                unsigned long long a = keys[t], bq = keys[ixj];
                if ((a > bq) == up) { keys[t] = bq; keys[ixj] = a; }
            }
            __syncthreads();
        }
        key = keys[t];
#pragma unroll
        for (int j = 16; j >= 1; j >>= 1) {
            unsigned long long part = __shfl_xor_sync(0xffffffffu, key, j);
            bool takeMin = (((t & j) == 0) == ((t & kk) == 0));
            key = takeMin ? (key < part ? key : part) : (key > part ? key : part);
        }
        keys[t] = key;
        __syncthreads();
    }

    if (t < k) {
        int sel = (int)(keys[t] & 0xffffffffu);
        newid[base + sel] = g * k + t;
        sel_s[t] = sel;
        tv_s[t] = tanhf(score[base + sel]);
    }
    __syncthreads();

    int total = k * Hd;
    for (int idx = t; idx < total; idx += n_per) {
        int rank = idx >> 7, f = idx & 127;
        xs[((long)(g * k + rank)) * Hd + f] =
            x[((long)(base + sel_s[rank])) * Hd + f] * tv_s[rank];
    }
    __syncthreads();

    if (t < 128) {
        const float* pr = xs + (long)g * k * Hd + t;
        float mx = -3.402823466e+38f, sm = 0.f;
        for (int r = 0; r < k; r++) {
            float v = pr[(long)r * Hd];
            mx = fmaxf(mx, v);
            sm += v;
        }
        float mean = sm / (float)k;
        if (addFlag) { out[g*256 + t] += mx; out[g*256 + 128 + t] += mean; }
        else         { out[g*256 + t]  = mx; out[g*256 + 128 + t]  = mean; }
    }
}

// ---- edge compaction (relabel + filter) + histogram of next layer ----------
__global__ void compact_k(const int* __restrict__ row, const int* __restrict__ col,
                          const int* __restrict__ newid,
                          int* __restrict__ orow, int* __restrict__ ocol,
                          int* __restrict__ cnt_next, int* __restrict__ counter,
                          const int* __restrict__ boundPtr, int maxE) {
    int e = blockIdx.x * blockDim.x + threadIdx.x;
    int bound = boundPtr ? __ldg(boundPtr) : maxE;
    bool valid = (e < bound);
    int nr = -1, nc = -1;
    if (valid) {
        nr = newid[row[e]];
        nc = newid[col[e]];
        valid = (nr >= 0) && (nc >= 0);
    }
    unsigned m = __ballot_sync(0xffffffffu, valid);
    if (valid) {
        int lane = threadIdx.x & 31;
        int leader = __ffs(m) - 1;
        int prefix = __popc(m & ((1u << lane) - 1u));
        int basep = 0;
        if (lane == leader) basep = atomicAdd(counter, __popc(m));
        basep = __shfl_sync(m, basep, leader);
        int pos = basep + prefix;
        orow[pos] = nr;
        ocol[pos] = nc;
        atomicAdd(&cnt_next[nc], 1);
    }
}

// ------------------------------- driver ------------------------------------
static inline int ceil_div(int a, int b) { return (a + b - 1) / b; }

struct Scratch {
    float *h, *cv, *xs1, *xs2, *xs3, *dinv, *sc, *pinv, *bf;
    int *nid, *cnt, *start, *cursor, *src, *r0, *c0, *r1, *c1, *nE;
    unsigned long long *ts;
};

extern "C" void kernel_launch(void* const* d_in, const int* in_sizes, int n_in,
                              void* d_out, int out_size)
{
    const float* x    = (const float*)d_in[0];
    const int*   erow = (const int*)  d_in[1];
    const int*   ecol = (const int*)  d_in[2];
    const float* W1 = (const float*)d_in[3],  *b1 = (const float*)d_in[4],  *p1 = (const float*)d_in[5];
    const float* W2 = (const float*)d_in[6],  *b2 = (const float*)d_in[7],  *p2 = (const float*)d_in[8];
    const float* W3 = (const float*)d_in[9],  *b3 = (const float*)d_in[10], *p3 = (const float*)d_in[11];
    float* out = (float*)d_out;
    const int E = in_sizes[1];

    Scratch S;
    cudaGetSymbolAddress((void**)&S.h,      g_h);
    cudaGetSymbolAddress((void**)&S.cv,     g_cv);
    cudaGetSymbolAddress((void**)&S.xs1,    g_xs1);
    cudaGetSymbolAddress((void**)&S.xs2,    g_xs2);
    cudaGetSymbolAddress((void**)&S.xs3,    g_xs3);
    cudaGetSymbolAddress((void**)&S.bf,     g_bf);
    cudaGetSymbolAddress((void**)&S.dinv,   g_dinv);
    cudaGetSymbolAddress((void**)&S.sc,     g_sc);
    cudaGetSymbolAddress((void**)&S.pinv,   g_pinv);
    cudaGetSymbolAddress((void**)&S.nid,    g_newid);
    cudaGetSymbolAddress((void**)&S.cnt,    g_cnt);
    cudaGetSymbolAddress((void**)&S.start,  g_start);
    cudaGetSymbolAddress((void**)&S.cursor, g_cursor);
    cudaGetSymbolAddress((void**)&S.ts,     g_tstate);
    cudaGetSymbolAddress((void**)&S.src,    g_src);
    cudaGetSymbolAddress((void**)&S.r0,     g_r0);
    cudaGetSymbolAddress((void**)&S.c0,     g_c0);
    cudaGetSymbolAddress((void**)&S.r1,     g_r1);
    cudaGetSymbolAddress((void**)&S.c1,     g_c1);
    cudaGetSymbolAddress((void**)&S.nE,     g_nE);

    // ---------------- Layer 1: n=131072, keep 512/1024 ----------------
    wsplit_k<<<779, 128>>>(W1, W2, W3, p1, p2, p3, S.bf, S.cnt, S.cursor, S.ts); // 1
    hist_k<<<ceil_div(E, 256), 256>>>(ecol, S.cnt, E);                           // 2
    scan_k<<<NN1 / 1024, 1024>>>(S.cnt, S.start, S.dinv, S.ts);                  // 3
    fill_k<<<ceil_div(E, 256), 256>>>(erow, ecol, S.start, S.cursor, S.src,
                                      nullptr, E);                               // 4
    gemm_mma<<<NN1 / 128, 256>>>(x, S.bf, S.cnt, S.h);                           // 5
    gather_k<<<ceil_div(NN1 * 32, 256), 256>>>(S.h, S.start, S.cnt, S.src,
                                               S.dinv, b1, p1, S.pinv + 0,
                                               S.cv, S.sc, NN1);                 // 6
    topk_k<<<Bg, 1024>>>(S.cv, S.sc, S.xs1, S.nid, 1024, 512, out, 0,
                         S.cnt, S.cursor, S.nE + 0, NN2);
    compact_k<<<ceil_div(E, 256), 256>>>(erow, ecol, S.nid, S.r0, S.c0,
                                         S.cnt, S.nE + 0, nullptr, E);

    // ---------------- Layer 2: n=65536, keep 256/512 ----------------
    gemm_mma<<<NN2 / 128, 256>>>(S.xs1, S.bf + 32768, S.cnt, S.h);
    scan_k<<<NN2 / 1024, 1024>>>(S.cnt, S.start, S.dinv, S.ts + 128);
    fill_k<<<ceil_div(E, 256), 256>>>(S.r0, S.c0, S.start, S.cursor, S.src,
                                      S.nE + 0, E);
    gather_k<<<ceil_div(NN2 * 32, 256), 256>>>(S.h, S.start, S.cnt, S.src,
                                               S.dinv, b2, p2, S.pinv + 1,
                                               S.cv, S.sc, NN2);
    topk_k<<<Bg, 512>>>(S.cv, S.sc, S.xs2, S.nid, 512, 256, out, 1,
                        S.cnt, S.cursor, S.nE + 1, NN3);
    compact_k<<<ceil_div(E, 256), 256>>>(S.r0, S.c0, S.nid, S.r1, S.c1,
                                         S.cnt, S.nE + 1, S.nE + 0, E);

    // ---------------- Layer 3: n=32768, keep 128/256 ----------------
    gemm_mma<<<NN3 / 128, 256>>>(S.xs2, S.bf + 65536, S.cnt, S.h);
    scan_k<<<NN3 / 1024, 1024>>>(S.cnt, S.start, S.dinv, S.ts + 256);
    fill_k<<<ceil_div(E, 256), 256>>>(S.r1, S.c1, S.start, S.cursor, S.src,
                                      S.nE + 1, E);
    gather_k<<<ceil_div(NN3 * 32, 256), 256>>>(S.h, S.start, S.cnt, S.src,
                                               S.dinv, b3, p3, S.pinv + 2,
                                               S.cv, S.sc, NN3);
    topk_k<<<Bg, 256>>>(S.cv, S.sc, S.xs3, S.nid, 256, 128, out, 1,
                        nullptr, nullptr, nullptr, 0);
}

// round 15
// speedup vs baseline: 1.0150x; 1.0150x over previous
#include <cuda_runtime.h>
#include <cuda_bf16.h>
#include <cstdint>
#include <math.h>

// ---------------------------------------------------------------------------
// GCN + TopK pooling stack (3 layers), B=128 graphs, N=1024 nodes, H=128.
// GEMM: mma.sync m16n8k8 tf32 3-term split (R12 smem-staged version).
// Single-kernel lookback scan. Warp-shfl bitonic topk + parallel readout.
// ---------------------------------------------------------------------------

#define Bg   128
#define Npg  1024
#define Hd   128
#define NN1  (Bg*Npg)        // 131072
#define NN2  (Bg*512)        // 65536
#define NN3  (Bg*256)        // 32768
#define EMAX 1048576

// ------------------------- device scratch (no allocs) ----------------------
__device__ __align__(128) float g_h [NN1*Hd];
__device__ __align__(128) float g_cv[NN1*Hd];
__device__ __align__(128) float g_xs1[NN2*Hd];
__device__ __align__(128) float g_xs2[NN3*Hd];
__device__ __align__(128) float g_xs3[(Bg*128)*Hd];
__device__ __align__(16) float g_bf[3*32768];   // W frags {hi0,hi1,lo0,lo1}
__device__ float g_dinv[NN1];
__device__ float g_sc[NN1];
__device__ int   g_newid[NN1];
__device__ int   g_cnt[NN1];
__device__ int   g_start[NN1];
__device__ int   g_cursor[NN1];
__device__ unsigned long long g_tstate[3*128];   // lookback scan states
__device__ int   g_src[EMAX];
__device__ int   g_r0[EMAX], g_c0[EMAX];
__device__ int   g_r1[EMAX], g_c1[EMAX];
__device__ int   g_nE[2];
__device__ float g_pinv[3];

// --------------------------- helpers ----------------------------------------
__device__ __forceinline__ float tf32r(float v) {
    float h;
    asm("cvt.rna.tf32.f32 %0, %1;" : "=f"(h) : "f"(v));
    return h;
}

__device__ __forceinline__ void mma8(float* c, const float4 a, const float2 b) {
    asm volatile(
        "mma.sync.aligned.m16n8k8.row.col.f32.tf32.tf32.f32 "
        "{%0,%1,%2,%3}, {%4,%5,%6,%7}, {%8,%9}, {%0,%1,%2,%3};"
        : "+f"(c[0]), "+f"(c[1]), "+f"(c[2]), "+f"(c[3])
        : "r"(__float_as_uint(a.x)), "r"(__float_as_uint(a.y)),
          "r"(__float_as_uint(a.z)), "r"(__float_as_uint(a.w)),
          "r"(__float_as_uint(b.x)), "r"(__float_as_uint(b.y)));
}

// ---- W frag split + pnorm + replay zero-init, one kernel (grid 779) --------
__global__ void wsplit_k(const float* __restrict__ W1, const float* __restrict__ W2,
                         const float* __restrict__ W3,
                         const float* __restrict__ p1, const float* __restrict__ p2,
                         const float* __restrict__ p3,
                         float* __restrict__ bf, int* __restrict__ cnt,
                         int* __restrict__ cursor, unsigned long long* __restrict__ ts) {
    __shared__ float sp[128];
    int bid = blockIdx.x, t = threadIdx.x;
    if (bid < 768) {
        int layer = bid >> 8;
        int idx = (bid & 255) * 128 + t;          // 0..32767
        const float* W = (layer == 0) ? W1 : (layer == 1) ? W2 : W3;
        int j  = idx & 3;
        int l  = (idx >> 2) & 31;
        int ks = (idx >> 7) & 3;
        int nt = (idx >> 9) & 15;
        int kc = idx >> 13;
        int k = kc * 32 + ks * 8 + (l & 3) + ((j & 1) << 2);
        int n = nt * 8 + (l >> 2);
        float v = W[k * 128 + n];
        float h = tf32r(v);
        bf[layer * 32768 + idx] = (j < 2) ? h : (v - h);
    } else if (bid < 771) {
        const float* p = (bid == 768) ? p1 : (bid == 769) ? p2 : p3;
        float v = p[t];
        sp[t] = v * v;
        __syncthreads();
        for (int o = 64; o > 0; o >>= 1) {
            if (t < o) sp[t] += sp[t + o];
            __syncthreads();
        }
        if (t == 0) g_pinv[bid - 768] = rsqrtf(sp[0]);
    } else {
        int z = (bid - 771) * 128 + t;            // 0..1023
        int4 z4 = make_int4(0, 0, 0, 0);
        for (int q = z; q < NN1 / 4; q += 1024) {
            ((int4*)cnt)[q] = z4;
            ((int4*)cursor)[q] = z4;
        }
        if (z < 384) ts[z] = 0ull;
    }
}

// --------------------------- mma.sync GEMM (R12 version) --------------------
__global__ void __launch_bounds__(256, 2)
gemm_mma(const float* __restrict__ X, const float* __restrict__ Bf,
         const int* __restrict__ cnt, float* __restrict__ Out)
{
    __shared__ float sA[8*4*32*8];   // [mt][ks][lane][8] {ah0..3, al0..3} 32KB
    __shared__ float sB[16*4*32*4];  // [nt][ks][lane][4] {bh0,bh1,bl0,bl1} 32KB
    const int tid = threadIdx.x;
    const int w = tid >> 5, l = tid & 31;
    const long row0 = (long)blockIdx.x * 128;

    float acc[16][4];
#pragma unroll
    for (int nt = 0; nt < 16; nt++)
#pragma unroll
        for (int j = 0; j < 4; j++) acc[nt][j] = 0.f;

    for (int kc = 0; kc < 4; kc++) {
        __syncthreads();
#pragma unroll
        for (int i = 0; i < 4; i++) {
            int f = tid + i * 256;
            int fl = f & 31, ks = (f >> 5) & 3, mt = f >> 7;
            long row = row0 + mt * 16 + (fl >> 2);
            int k = kc * 32 + ks * 8 + (fl & 3);
            float v0 = X[row * 128 + k];
            float v1 = X[(row + 8) * 128 + k];
            float v2 = X[row * 128 + k + 4];
            float v3 = X[(row + 8) * 128 + k + 4];
            float h0 = tf32r(v0), h1 = tf32r(v1), h2 = tf32r(v2), h3 = tf32r(v3);
            int o = f * 8;
            *(float4*)&sA[o]     = make_float4(h0, h1, h2, h3);
            *(float4*)&sA[o + 4] = make_float4(v0 - h0, v1 - h1, v2 - h2, v3 - h3);
        }
        const float4* sbf = (const float4*)(Bf + kc * 8192);
#pragma unroll
        for (int i = 0; i < 8; i++) {
            int f = tid + i * 256;
            ((float4*)sB)[f] = sbf[f];
        }
        __syncthreads();

#pragma unroll
        for (int ks = 0; ks < 4; ks++) {
            const float4* ap = (const float4*)&sA[((w * 4 + ks) * 32 + l) * 8];
            float4 ah = ap[0];
            float4 al = ap[1];
#pragma unroll
            for (int nt = 0; nt < 16; nt++) {
                float4 bq = *(const float4*)&sB[((nt * 4 + ks) * 32 + l) * 4];
                float2 bh = make_float2(bq.x, bq.y);
                float2 bl = make_float2(bq.z, bq.w);
                mma8(acc[nt], ah, bh);
                mma8(acc[nt], ah, bl);
                mma8(acc[nt], al, bh);
            }
        }
    }

    int r0 = (int)row0 + w * 16 + (l >> 2);
    float dv0 = rsqrtf((float)__ldg(&cnt[r0]) + 1.0f);
    float dv1 = rsqrtf((float)__ldg(&cnt[r0 + 8]) + 1.0f);
#pragma unroll
    for (int nt = 0; nt < 16; nt++) {
        int col = nt * 8 + (l & 3) * 2;
        *(float2*)&Out[(long)r0 * 128 + col] =
            make_float2(acc[nt][0] * dv0, acc[nt][1] * dv0);
        *(float2*)&Out[(long)(r0 + 8) * 128 + col] =
            make_float2(acc[nt][2] * dv1, acc[nt][3] * dv1);
    }
}

// --------------------------- hist -------------------------------------------
__global__ void hist_k(const int* __restrict__ col, int* __restrict__ cnt, int nE) {
    int i = blockIdx.x * blockDim.x + threadIdx.x;
    if (i < nE) atomicAdd(&cnt[col[i]], 1);
}

// ---- single-kernel exclusive scan (decoupled lookback; grid <= 128) --------
__global__ void scan_k(const int* __restrict__ cnt, int* __restrict__ start,
                       float* __restrict__ dinv, unsigned long long* __restrict__ st)
{
    __shared__ int s[1024];
    __shared__ int s_prefix;
    int t = threadIdx.x, b = blockIdx.x;
    int i = b * 1024 + t;
    int v = cnt[i];
    s[t] = v;
    __syncthreads();
    for (int o = 1; o < 1024; o <<= 1) {
        int add = (t >= o) ? s[t - o] : 0;
        __syncthreads();
        s[t] += add;
        __syncthreads();
    }
    if (t == 0) {
        int total = s[1023];
        atomicExch(&st[b], (((unsigned long long)total) << 2) | 1ull);  // PARTIAL
        int ex = 0;
        for (int j = b - 1; j >= 0; j--) {
            unsigned long long f;
            do { f = atomicAdd(&st[j], 0ull); } while ((f & 3ull) == 0ull);
            ex += (int)(f >> 2);
            if ((f & 3ull) == 2ull) break;       // PREFIX: inclusive, stop
        }
        atomicExch(&st[b], (((unsigned long long)(ex + total)) << 2) | 2ull);
        s_prefix = ex;
    }
    __syncthreads();
    start[i] = s[t] - v + s_prefix;
    dinv[i] = rsqrtf((float)v + 1.0f);
}

__global__ void fill_k(const int* __restrict__ row, const int* __restrict__ col,
                       const int* __restrict__ start, int* __restrict__ cursor,
                       int* __restrict__ src, const int* __restrict__ boundPtr,
                       int maxE) {
    int i = blockIdx.x * blockDim.x + threadIdx.x;
    int bound = boundPtr ? __ldg(boundPtr) : maxE;
    if (i >= bound) return;
    int c = col[i];
    int p = atomicAdd(&cursor[c], 1);
    src[start[c] + p] = row[i];
}

// ---- gather (h is dinv-prescaled) + self + bias + relu + score, fused ------
__global__ void gather_k(const float* __restrict__ h, const int* __restrict__ start,
                         const int* __restrict__ cnt, const int* __restrict__ src,
                         const float* __restrict__ dinv, const float* __restrict__ b,
                         const float* __restrict__ p, const float* __restrict__ pinv,
                         float* __restrict__ out, float* __restrict__ score, int n) {
    int w = (blockIdx.x * blockDim.x + threadIdx.x) >> 5;
    if (w >= n) return;
    int lane = threadIdx.x & 31;
    float dc = dinv[w];
    int s0 = start[w], d = cnt[w];
    float4 acc = ((const float4*)(h + (long)w * Hd))[lane];

    int e = 0;
    for (; e + 4 <= d; e += 4) {
        int r0 = __ldg(&src[s0 + e]);
        int r1 = __ldg(&src[s0 + e + 1]);
        int r2 = __ldg(&src[s0 + e + 2]);
        int r3 = __ldg(&src[s0 + e + 3]);
        float4 v0 = ((const float4*)(h + (long)r0 * Hd))[lane];
        float4 v1 = ((const float4*)(h + (long)r1 * Hd))[lane];
        float4 v2 = ((const float4*)(h + (long)r2 * Hd))[lane];
        float4 v3 = ((const float4*)(h + (long)r3 * Hd))[lane];
        acc.x += v0.x + v1.x + v2.x + v3.x;
        acc.y += v0.y + v1.y + v2.y + v3.y;
        acc.z += v0.z + v1.z + v2.z + v3.z;
        acc.w += v0.w + v1.w + v2.w + v3.w;
    }
    for (; e < d; e++) {
        int r = __ldg(&src[s0 + e]);
        float4 v = ((const float4*)(h + (long)r * Hd))[lane];
        acc.x += v.x; acc.y += v.y; acc.z += v.z; acc.w += v.w;
    }

    float4 bv = ((const float4*)b)[lane];
    acc.x = fmaxf(fmaf(acc.x, dc, bv.x), 0.f);
    acc.y = fmaxf(fmaf(acc.y, dc, bv.y), 0.f);
    acc.z = fmaxf(fmaf(acc.z, dc, bv.z), 0.f);
    acc.w = fmaxf(fmaf(acc.w, dc, bv.w), 0.f);
    ((float4*)(out + (long)w * Hd))[lane] = acc;

    float4 pv = ((const float4*)p)[lane];
    float s = acc.x*pv.x + acc.y*pv.y + acc.z*pv.z + acc.w*pv.w;
#pragma unroll
    for (int o = 16; o; o >>= 1) s += __shfl_xor_sync(0xffffffffu, s, o);
    if (lane == 0) score[w] = s * __ldg(pinv);
}

// ------- top-k (matches jax.lax.top_k) + parallel readout + zero-init -------
__global__ void topk_k(const float* __restrict__ x, const float* __restrict__ score,
                       float* __restrict__ xs, int* __restrict__ newid,
                       int n_per, int k,
                       float* __restrict__ out, int addFlag,
                       int* __restrict__ cnt_next, int* __restrict__ cursor_next,
                       int* __restrict__ counter_next, int n_next) {
    __shared__ unsigned long long keys[1024];
    __shared__ float tv_s[512];
    __shared__ int   sel_s[512];
    int g = blockIdx.x, t = threadIdx.x;
    int base = g * n_per;
    int gid = base + t;

    if (n_next > 0) {
        if (gid < n_next) { cnt_next[gid] = 0; cursor_next[gid] = 0; }
        if (gid == 0) *counter_next = 0;
    }

    newid[gid] = -1;
    float s = score[gid];
    unsigned int fb = __float_as_uint(s);
    unsigned int mp = (fb & 0x80000000u) ? ~fb : (fb | 0x80000000u);
    unsigned long long key = ((unsigned long long)(~mp) << 32) | (unsigned int)t;

#pragma unroll
    for (int kk = 2; kk <= 32; kk <<= 1) {
#pragma unroll
        for (int j = kk >> 1; j >= 1; j >>= 1) {
            unsigned long long part = __shfl_xor_sync(0xffffffffu, key, j);
            bool takeMin = (((t & j) == 0) == ((t & kk) == 0));
            key = takeMin ? (key < part ? key : part) : (key > part ? key : part);
        }
    }
    keys[t] = key;
    __syncthreads();

    for (int kk = 64; kk <= n_per; kk <<= 1) {
        for (int j = kk >> 1; j >= 32; j >>= 1) {
            int ixj = t ^ j;
            if (ixj > t) {
                bool up = ((t & kk) == 0);
                unsigned long long a = keys[t], bq = keys[ixj];
                if ((a > bq) == up) { keys[t] = bq; keys[ixj] = a; }
            }
            __syncthreads();
        }
        key = keys[t];
#pragma unroll
        for (int j = 16; j >= 1; j >>= 1) {
            unsigned long long part = __shfl_xor_sync(0xffffffffu, key, j);
            bool takeMin = (((t & j) == 0) == ((t & kk) == 0));
            key = takeMin ? (key < part ? key : part) : (key > part ? key : part);
        }
        keys[t] = key;
        __syncthreads();
    }

    if (t < k) {
        int sel = (int)(keys[t] & 0xffffffffu);
        newid[base + sel] = g * k + t;
        sel_s[t] = sel;
        tv_s[t] = tanhf(score[base + sel]);
    }
    __syncthreads();

    int total = k * Hd;
    for (int idx = t; idx < total; idx += n_per) {
        int rank = idx >> 7, f = idx & 127;
        xs[((long)(g * k + rank)) * Hd + f] =
            x[((long)(base + sel_s[rank])) * Hd + f] * tv_s[rank];
    }
    __syncthreads();

    // parallel readout: thread = (feature f, rank-group gr); groups stride ranks.
    // keys buffer (8KB = 2048 floats) is retired; reuse as reduction scratch.
    {
        float* rf = (float*)keys;          // rf[0..1023] = max, rf[1024..2047] = sum
        int ngr = n_per >> 7;              // groups: 8 / 4 / 2
        int f = t & 127, gr = t >> 7;
        float mx = -3.402823466e+38f, sm = 0.f;
        const float* xg = xs + (long)g * k * Hd + f;
        for (int r = gr; r < k; r += ngr) {
            float v = xg[(long)r * Hd];
            mx = fmaxf(mx, v);
            sm += v;
        }
        rf[t] = mx;
        rf[1024 + t] = sm;
        __syncthreads();
        if (t < 128) {
            float m = rf[t], s2 = rf[1024 + t];
            for (int q = 1; q < ngr; q++) {
                m  = fmaxf(m, rf[q * 128 + t]);
                s2 += rf[1024 + q * 128 + t];
            }
            float mean = s2 / (float)k;
            if (addFlag) { out[g*256 + t] += m; out[g*256 + 128 + t] += mean; }
            else         { out[g*256 + t]  = m; out[g*256 + 128 + t]  = mean; }
        }
    }
}

// ---- edge compaction (relabel + filter) + histogram of next layer ----------
__global__ void compact_k(const int* __restrict__ row, const int* __restrict__ col,
                          const int* __restrict__ newid,
                          int* __restrict__ orow, int* __restrict__ ocol,
                          int* __restrict__ cnt_next, int* __restrict__ counter,
                          const int* __restrict__ boundPtr, int maxE) {
    int e = blockIdx.x * blockDim.x + threadIdx.x;
    int bound = boundPtr ? __ldg(boundPtr) : maxE;
    bool valid = (e < bound);
    int nr = -1, nc = -1;
    if (valid) {
        nr = newid[row[e]];
        nc = newid[col[e]];
        valid = (nr >= 0) && (nc >= 0);
    }
    unsigned m = __ballot_sync(0xffffffffu, valid);
    if (valid) {
        int lane = threadIdx.x & 31;
        int leader = __ffs(m) - 1;
        int prefix = __popc(m & ((1u << lane) - 1u));
        int basep = 0;
        if (lane == leader) basep = atomicAdd(counter, __popc(m));
        basep = __shfl_sync(m, basep, leader);
        int pos = basep + prefix;
        orow[pos] = nr;
        ocol[pos] = nc;
        atomicAdd(&cnt_next[nc], 1);
    }
}

// ------------------------------- driver ------------------------------------
static inline int ceil_div(int a, int b) { return (a + b - 1) / b; }

struct Scratch {
    float *h, *cv, *xs1, *xs2, *xs3, *dinv, *sc, *pinv, *bf;
    int *nid, *cnt, *start, *cursor, *src, *r0, *c0, *r1, *c1, *nE;
    unsigned long long *ts;
};

extern "C" void kernel_launch(void* const* d_in, const int* in_sizes, int n_in,
                              void* d_out, int out_size)
{
    const float* x    = (const float*)d_in[0];
    const int*   erow = (const int*)  d_in[1];
    const int*   ecol = (const int*)  d_in[2];
    const float* W1 = (const float*)d_in[3],  *b1 = (const float*)d_in[4],  *p1 = (const float*)d_in[5];
    const float* W2 = (const float*)d_in[6],  *b2 = (const float*)d_in[7],  *p2 = (const float*)d_in[8];
    const float* W3 = (const float*)d_in[9],  *b3 = (const float*)d_in[10], *p3 = (const float*)d_in[11];
    float* out = (float*)d_out;
    const int E = in_sizes[1];

    Scratch S;
    cudaGetSymbolAddress((void**)&S.h,      g_h);
    cudaGetSymbolAddress((void**)&S.cv,     g_cv);
    cudaGetSymbolAddress((void**)&S.xs1,    g_xs1);
    cudaGetSymbolAddress((void**)&S.xs2,    g_xs2);
    cudaGetSymbolAddress((void**)&S.xs3,    g_xs3);
    cudaGetSymbolAddress((void**)&S.bf,     g_bf);
    cudaGetSymbolAddress((void**)&S.dinv,   g_dinv);
    cudaGetSymbolAddress((void**)&S.sc,     g_sc);
    cudaGetSymbolAddress((void**)&S.pinv,   g_pinv);
    cudaGetSymbolAddress((void**)&S.nid,    g_newid);
    cudaGetSymbolAddress((void**)&S.cnt,    g_cnt);
    cudaGetSymbolAddress((void**)&S.start,  g_start);
    cudaGetSymbolAddress((void**)&S.cursor, g_cursor);
    cudaGetSymbolAddress((void**)&S.ts,     g_tstate);
    cudaGetSymbolAddress((void**)&S.src,    g_src);
    cudaGetSymbolAddress((void**)&S.r0,     g_r0);
    cudaGetSymbolAddress((void**)&S.c0,     g_c0);
    cudaGetSymbolAddress((void**)&S.r1,     g_r1);
    cudaGetSymbolAddress((void**)&S.c1,     g_c1);
    cudaGetSymbolAddress((void**)&S.nE,     g_nE);

    // ---------------- Layer 1: n=131072, keep 512/1024 ----------------
    wsplit_k<<<779, 128>>>(W1, W2, W3, p1, p2, p3, S.bf, S.cnt, S.cursor, S.ts); // 1
    hist_k<<<ceil_div(E, 256), 256>>>(ecol, S.cnt, E);                           // 2
    scan_k<<<NN1 / 1024, 1024>>>(S.cnt, S.start, S.dinv, S.ts);                  // 3
    fill_k<<<ceil_div(E, 256), 256>>>(erow, ecol, S.start, S.cursor, S.src,
                                      nullptr, E);                               // 4
    gemm_mma<<<NN1 / 128, 256>>>(x, S.bf, S.cnt, S.h);                           // 5
    gather_k<<<ceil_div(NN1 * 32, 256), 256>>>(S.h, S.start, S.cnt, S.src,
                                               S.dinv, b1, p1, S.pinv + 0,
                                               S.cv, S.sc, NN1);                 // 6
    topk_k<<<Bg, 1024>>>(S.cv, S.sc, S.xs1, S.nid, 1024, 512, out, 0,
                         S.cnt, S.cursor, S.nE + 0, NN2);
    compact_k<<<ceil_div(E, 256), 256>>>(erow, ecol, S.nid, S.r0, S.c0,
                                         S.cnt, S.nE + 0, nullptr, E);

    // ---------------- Layer 2: n=65536, keep 256/512 ----------------
    gemm_mma<<<NN2 / 128, 256>>>(S.xs1, S.bf + 32768, S.cnt, S.h);
    scan_k<<<NN2 / 1024, 1024>>>(S.cnt, S.start, S.dinv, S.ts + 128);
    fill_k<<<ceil_div(E, 256), 256>>>(S.r0, S.c0, S.start, S.cursor, S.src,
                                      S.nE + 0, E);
    gather_k<<<ceil_div(NN2 * 32, 256), 256>>>(S.h, S.start, S.cnt, S.src,
                                               S.dinv, b2, p2, S.pinv + 1,
                                               S.cv, S.sc, NN2);
    topk_k<<<Bg, 512>>>(S.cv, S.sc, S.xs2, S.nid, 512, 256, out, 1,
                        S.cnt, S.cursor, S.nE + 1, NN3);
    compact_k<<<ceil_div(E, 256), 256>>>(S.r0, S.c0, S.nid, S.r1, S.c1,
                                         S.cnt, S.nE + 1, S.nE + 0, E);

    // ---------------- Layer 3: n=32768, keep 128/256 ----------------
    gemm_mma<<<NN3 / 128, 256>>>(S.xs2, S.bf + 65536, S.cnt, S.h);
    scan_k<<<NN3 / 1024, 1024>>>(S.cnt, S.start, S.dinv, S.ts + 256);
    fill_k<<<ceil_div(E, 256), 256>>>(S.r1, S.c1, S.start, S.cursor, S.src,
                                      S.nE + 1, E);
    gather_k<<<ceil_div(NN3 * 32, 256), 256>>>(S.h, S.start, S.cnt, S.src,
                                               S.dinv, b3, p3, S.pinv + 2,
                                               S.cv, S.sc, NN3);
    topk_k<<<Bg, 256>>>(S.cv, S.sc, S.xs3, S.nid, 256, 128, out, 1,
                        nullptr, nullptr, nullptr, 0);
}

// round 17
// speedup vs baseline: 1.1345x; 1.1177x over previous
#include <cuda_runtime.h>
#include <cuda_bf16.h>
#include <cstdint>
#include <math.h>

// ---------------------------------------------------------------------------
// GCN + TopK pooling stack (3 layers), B=128 graphs, N=1024 nodes, H=128.
// GEMM: mma.sync m16n8k8 tf32 3-term split (R12 smem-staged version),
// decoupled from the edge pipeline and overlapped with it via a second
// stream (graph-capture fork/join). Single-kernel lookback scan.
// Warp-shfl bitonic topk.
// ---------------------------------------------------------------------------

#define Bg   128
#define Npg  1024
#define Hd   128
#define NN1  (Bg*Npg)        // 131072
#define NN2  (Bg*512)        // 65536
#define NN3  (Bg*256)        // 32768
#define EMAX 1048576

// ------------------------- device scratch (no allocs) ----------------------
__device__ __align__(128) float g_h [NN1*Hd];   // h = x @ W (unscaled)
__device__ __align__(128) float g_cv[NN1*Hd];
__device__ __align__(128) float g_xs1[NN2*Hd];
__device__ __align__(128) float g_xs2[NN3*Hd];
__device__ __align__(128) float g_xs3[(Bg*128)*Hd];
__device__ __align__(16) float g_bf[3*32768];   // W frags {hi0,hi1,lo0,lo1}
__device__ float g_dinv[NN1];
__device__ float g_sc[NN1];
__device__ int   g_newid[NN1];
__device__ int   g_cnt[NN1];
__device__ int   g_start[NN1];
__device__ int   g_cursor[NN1];
__device__ unsigned long long g_tstate[3*128];   // lookback scan states
__device__ int   g_src[EMAX];
__device__ int   g_r0[EMAX], g_c0[EMAX];
__device__ int   g_r1[EMAX], g_c1[EMAX];
__device__ int   g_nE[2];
__device__ float g_pinv[3];

// --------------------------- helpers ----------------------------------------
__device__ __forceinline__ float tf32r(float v) {
    float h;
    asm("cvt.rna.tf32.f32 %0, %1;" : "=f"(h) : "f"(v));
    return h;
}

__device__ __forceinline__ void mma8(float* c, const float4 a, const float2 b) {
    asm volatile(
        "mma.sync.aligned.m16n8k8.row.col.f32.tf32.tf32.f32 "
        "{%0,%1,%2,%3}, {%4,%5,%6,%7}, {%8,%9}, {%0,%1,%2,%3};"
        : "+f"(c[0]), "+f"(c[1]), "+f"(c[2]), "+f"(c[3])
        : "r"(__float_as_uint(a.x)), "r"(__float_as_uint(a.y)),
          "r"(__float_as_uint(a.z)), "r"(__float_as_uint(a.w)),
          "r"(__float_as_uint(b.x)), "r"(__float_as_uint(b.y)));
}

// ---- W frag split + pnorm + replay zero-init, one kernel (grid 779) --------
__global__ void wsplit_k(const float* __restrict__ W1, const float* __restrict__ W2,
                         const float* __restrict__ W3,
                         const float* __restrict__ p1, const float* __restrict__ p2,
                         const float* __restrict__ p3,
                         float* __restrict__ bf, int* __restrict__ cnt,
                         int* __restrict__ cursor, unsigned long long* __restrict__ ts) {
    __shared__ float sp[128];
    int bid = blockIdx.x, t = threadIdx.x;
    if (bid < 768) {
        int layer = bid >> 8;
        int idx = (bid & 255) * 128 + t;          // 0..32767
        const float* W = (layer == 0) ? W1 : (layer == 1) ? W2 : W3;
        int j  = idx & 3;
        int l  = (idx >> 2) & 31;
        int ks = (idx >> 7) & 3;
        int nt = (idx >> 9) & 15;
        int kc = idx >> 13;
        int k = kc * 32 + ks * 8 + (l & 3) + ((j & 1) << 2);
        int n = nt * 8 + (l >> 2);
        float v = W[k * 128 + n];
        float h = tf32r(v);
        bf[layer * 32768 + idx] = (j < 2) ? h : (v - h);
    } else if (bid < 771) {
        const float* p = (bid == 768) ? p1 : (bid == 769) ? p2 : p3;
        float v = p[t];
        sp[t] = v * v;
        __syncthreads();
        for (int o = 64; o > 0; o >>= 1) {
            if (t < o) sp[t] += sp[t + o];
            __syncthreads();
        }
        if (t == 0) g_pinv[bid - 768] = rsqrtf(sp[0]);
    } else {
        int z = (bid - 771) * 128 + t;            // 0..1023
        int4 z4 = make_int4(0, 0, 0, 0);
        for (int q = z; q < NN1 / 4; q += 1024) {
            ((int4*)cnt)[q] = z4;
            ((int4*)cursor)[q] = z4;
        }
        if (z < 384) ts[z] = 0ull;
    }
}

// --------------------------- mma.sync GEMM (R12 core, no dinv) --------------
__global__ void __launch_bounds__(256, 2)
gemm_mma(const float* __restrict__ X, const float* __restrict__ Bf,
         float* __restrict__ Out)
{
    __shared__ float sA[8*4*32*8];   // [mt][ks][lane][8] {ah0..3, al0..3} 32KB
    __shared__ float sB[16*4*32*4];  // [nt][ks][lane][4] {bh0,bh1,bl0,bl1} 32KB
    const int tid = threadIdx.x;
    const int w = tid >> 5, l = tid & 31;
    const long row0 = (long)blockIdx.x * 128;

    float acc[16][4];
#pragma unroll
    for (int nt = 0; nt < 16; nt++)
#pragma unroll
        for (int j = 0; j < 4; j++) acc[nt][j] = 0.f;

    for (int kc = 0; kc < 4; kc++) {
        __syncthreads();
#pragma unroll
        for (int i = 0; i < 4; i++) {
            int f = tid + i * 256;
            int fl = f & 31, ks = (f >> 5) & 3, mt = f >> 7;
            long row = row0 + mt * 16 + (fl >> 2);
            int k = kc * 32 + ks * 8 + (fl & 3);
            float v0 = X[row * 128 + k];
            float v1 = X[(row + 8) * 128 + k];
            float v2 = X[row * 128 + k + 4];
            float v3 = X[(row + 8) * 128 + k + 4];
            float h0 = tf32r(v0), h1 = tf32r(v1), h2 = tf32r(v2), h3 = tf32r(v3);
            int o = f * 8;
            *(float4*)&sA[o]     = make_float4(h0, h1, h2, h3);
            *(float4*)&sA[o + 4] = make_float4(v0 - h0, v1 - h1, v2 - h2, v3 - h3);
        }
        const float4* sbf = (const float4*)(Bf + kc * 8192);
#pragma unroll
        for (int i = 0; i < 8; i++) {
            int f = tid + i * 256;
            ((float4*)sB)[f] = sbf[f];
        }
        __syncthreads();

#pragma unroll
        for (int ks = 0; ks < 4; ks++) {
            const float4* ap = (const float4*)&sA[((w * 4 + ks) * 32 + l) * 8];
            float4 ah = ap[0];
            float4 al = ap[1];
#pragma unroll
            for (int nt = 0; nt < 16; nt++) {
                float4 bq = *(const float4*)&sB[((nt * 4 + ks) * 32 + l) * 4];
                float2 bh = make_float2(bq.x, bq.y);
                float2 bl = make_float2(bq.z, bq.w);
                mma8(acc[nt], ah, bh);
                mma8(acc[nt], ah, bl);
                mma8(acc[nt], al, bh);
            }
        }
    }

    int r0 = (int)row0 + w * 16 + (l >> 2);
#pragma unroll
    for (int nt = 0; nt < 16; nt++) {
        int col = nt * 8 + (l & 3) * 2;
        *(float2*)&Out[(long)r0 * 128 + col] =
            make_float2(acc[nt][0], acc[nt][1]);
        *(float2*)&Out[(long)(r0 + 8) * 128 + col] =
            make_float2(acc[nt][2], acc[nt][3]);
    }
}

// --------------------------- hist -------------------------------------------
__global__ void hist_k(const int* __restrict__ col, int* __restrict__ cnt, int nE) {
    int i = blockIdx.x * blockDim.x + threadIdx.x;
    if (i < nE) atomicAdd(&cnt[col[i]], 1);
}

// ---- single-kernel exclusive scan (decoupled lookback; grid <= 128) --------
__global__ void scan_k(const int* __restrict__ cnt, int* __restrict__ start,
                       float* __restrict__ dinv, unsigned long long* __restrict__ st)
{
    __shared__ int s[1024];
    __shared__ int s_prefix;
    int t = threadIdx.x, b = blockIdx.x;
    int i = b * 1024 + t;
    int v = cnt[i];
    s[t] = v;
    __syncthreads();
    for (int o = 1; o < 1024; o <<= 1) {
        int add = (t >= o) ? s[t - o] : 0;
        __syncthreads();
        s[t] += add;
        __syncthreads();
    }
    if (t == 0) {
        int total = s[1023];
        atomicExch(&st[b], (((unsigned long long)total) << 2) | 1ull);  // PARTIAL
        int ex = 0;
        for (int j = b - 1; j >= 0; j--) {
            unsigned long long f;
            do { f = atomicAdd(&st[j], 0ull); } while ((f & 3ull) == 0ull);
            ex += (int)(f >> 2);
            if ((f & 3ull) == 2ull) break;       // PREFIX: inclusive, stop
        }
        atomicExch(&st[b], (((unsigned long long)(ex + total)) << 2) | 2ull);
        s_prefix = ex;
    }
    __syncthreads();
    start[i] = s[t] - v + s_prefix;
    dinv[i] = rsqrtf((float)v + 1.0f);
}

__global__ void fill_k(const int* __restrict__ row, const int* __restrict__ col,
                       const int* __restrict__ start, int* __restrict__ cursor,
                       int* __restrict__ src, const int* __restrict__ boundPtr,
                       int maxE) {
    int i = blockIdx.x * blockDim.x + threadIdx.x;
    int bound = boundPtr ? __ldg(boundPtr) : maxE;
    if (i >= bound) return;
    int c = col[i];
    int p = atomicAdd(&cursor[c], 1);
    src[start[c] + p] = row[i];
}

// ---- gather + normalize + self + bias + relu + score, fused ----------------
// out = (sum_r dinv[r]*h[r] + dinv[w]*h[w]) * dinv[w] + b, relu'd.
__global__ void gather_k(const float* __restrict__ h, const int* __restrict__ start,
                         const int* __restrict__ cnt, const int* __restrict__ src,
                         const float* __restrict__ dinv, const float* __restrict__ b,
                         const float* __restrict__ p, const float* __restrict__ pinv,
                         float* __restrict__ out, float* __restrict__ score, int n) {
    int w = (blockIdx.x * blockDim.x + threadIdx.x) >> 5;
    if (w >= n) return;
    int lane = threadIdx.x & 31;
    float dc = dinv[w];
    int s0 = start[w], d = cnt[w];
    float4 hv = ((const float4*)(h + (long)w * Hd))[lane];
    float4 acc = make_float4(hv.x * dc, hv.y * dc, hv.z * dc, hv.w * dc);

    int e = 0;
    for (; e + 4 <= d; e += 4) {
        int r0 = __ldg(&src[s0 + e]);
        int r1 = __ldg(&src[s0 + e + 1]);
        int r2 = __ldg(&src[s0 + e + 2]);
        int r3 = __ldg(&src[s0 + e + 3]);
        float c0 = __ldg(&dinv[r0]), c1 = __ldg(&dinv[r1]);
        float c2 = __ldg(&dinv[r2]), c3 = __ldg(&dinv[r3]);
        float4 v0 = ((const float4*)(h + (long)r0 * Hd))[lane];
        float4 v1 = ((const float4*)(h + (long)r1 * Hd))[lane];
        float4 v2 = ((const float4*)(h + (long)r2 * Hd))[lane];
        float4 v3 = ((const float4*)(h + (long)r3 * Hd))[lane];
        acc.x = fmaf(v0.x, c0, acc.x); acc.y = fmaf(v0.y, c0, acc.y);
        acc.z = fmaf(v0.z, c0, acc.z); acc.w = fmaf(v0.w, c0, acc.w);
        acc.x = fmaf(v1.x, c1, acc.x); acc.y = fmaf(v1.y, c1, acc.y);
        acc.z = fmaf(v1.z, c1, acc.z); acc.w = fmaf(v1.w, c1, acc.w);
        acc.x = fmaf(v2.x, c2, acc.x); acc.y = fmaf(v2.y, c2, acc.y);
        acc.z = fmaf(v2.z, c2, acc.z); acc.w = fmaf(v2.w, c2, acc.w);
        acc.x = fmaf(v3.x, c3, acc.x); acc.y = fmaf(v3.y, c3, acc.y);
        acc.z = fmaf(v3.z, c3, acc.z); acc.w = fmaf(v3.w, c3, acc.w);
    }
    for (; e < d; e++) {
        int r = __ldg(&src[s0 + e]);
        float cr = __ldg(&dinv[r]);
        float4 v = ((const float4*)(h + (long)r * Hd))[lane];
        acc.x = fmaf(v.x, cr, acc.x); acc.y = fmaf(v.y, cr, acc.y);
        acc.z = fmaf(v.z, cr, acc.z); acc.w = fmaf(v.w, cr, acc.w);
    }

    float4 bv = ((const float4*)b)[lane];
    acc.x = fmaxf(fmaf(acc.x, dc, bv.x), 0.f);
    acc.y = fmaxf(fmaf(acc.y, dc, bv.y), 0.f);
    acc.z = fmaxf(fmaf(acc.z, dc, bv.z), 0.f);
    acc.w = fmaxf(fmaf(acc.w, dc, bv.w), 0.f);
    ((float4*)(out + (long)w * Hd))[lane] = acc;

    float4 pv = ((const float4*)p)[lane];
    float s = acc.x*pv.x + acc.y*pv.y + acc.z*pv.z + acc.w*pv.w;
#pragma unroll
    for (int o = 16; o; o >>= 1) s += __shfl_xor_sync(0xffffffffu, s, o);
    if (lane == 0) score[w] = s * __ldg(pinv);
}

// ------- top-k (matches jax.lax.top_k) + readout + next-layer zeroing -------
__global__ void topk_k(const float* __restrict__ x, const float* __restrict__ score,
                       float* __restrict__ xs, int* __restrict__ newid,
                       int n_per, int k,
                       float* __restrict__ out, int addFlag,
                       int* __restrict__ cnt_next, int* __restrict__ cursor_next,
                       int* __restrict__ counter_next, int n_next) {
    __shared__ unsigned long long keys[1024];
    __shared__ float tv_s[512];
    __shared__ int   sel_s[512];
    int g = blockIdx.x, t = threadIdx.x;
    int base = g * n_per;
    int gid = base + t;

    if (n_next > 0) {
        if (gid < n_next) { cnt_next[gid] = 0; cursor_next[gid] = 0; }
        if (gid == 0) *counter_next = 0;
    }

    newid[gid] = -1;
    float s = score[gid];
    unsigned int fb = __float_as_uint(s);
    unsigned int mp = (fb & 0x80000000u) ? ~fb : (fb | 0x80000000u);
    unsigned long long key = ((unsigned long long)(~mp) << 32) | (unsigned int)t;

#pragma unroll
    for (int kk = 2; kk <= 32; kk <<= 1) {
#pragma unroll
        for (int j = kk >> 1; j >= 1; j >>= 1) {
            unsigned long long part = __shfl_xor_sync(0xffffffffu, key, j);
            bool takeMin = (((t & j) == 0) == ((t & kk) == 0));
            key = takeMin ? (key < part ? key : part) : (key > part ? key : part);
        }
    }
    keys[t] = key;
    __syncthreads();

    for (int kk = 64; kk <= n_per; kk <<= 1) {
        for (int j = kk >> 1; j >= 32; j >>= 1) {
            int ixj = t ^ j;
            if (ixj > t) {
                bool up = ((t & kk) == 0);
                unsigned long long a = keys[t], bq = keys[ixj];
                if ((a > bq) == up) { keys[t] = bq; keys[ixj] = a; }
            }
            __syncthreads();
        }
        key = keys[t];
#pragma unroll
        for (int j = 16; j >= 1; j >>= 1) {
            unsigned long long part = __shfl_xor_sync(0xffffffffu, key, j);
            bool takeMin = (((t & j) == 0) == ((t & kk) == 0));
            key = takeMin ? (key < part ? key : part) : (key > part ? key : part);
        }
        keys[t] = key;
        __syncthreads();
    }

    if (t < k) {
        int sel = (int)(keys[t] & 0xffffffffu);
        newid[base + sel] = g * k + t;
        sel_s[t] = sel;
        tv_s[t] = tanhf(score[base + sel]);
    }
    __syncthreads();

    int total = k * Hd;
    for (int idx = t; idx < total; idx += n_per) {
        int rank = idx >> 7, f = idx & 127;
        xs[((long)(g * k + rank)) * Hd + f] =
            x[((long)(base + sel_s[rank])) * Hd + f] * tv_s[rank];
    }
    __syncthreads();

    if (t < 128) {
        const float* pr = xs + (long)g * k * Hd + t;
        float mx = -3.402823466e+38f, sm = 0.f;
        for (int r = 0; r < k; r++) {
            float v = pr[(long)r * Hd];
            mx = fmaxf(mx, v);
            sm += v;
        }
        float mean = sm / (float)k;
        if (addFlag) { out[g*256 + t] += mx; out[g*256 + 128 + t] += mean; }
        else         { out[g*256 + t]  = mx; out[g*256 + 128 + t]  = mean; }
    }
}

// ---- edge compaction (relabel + filter) + histogram of next layer ----------
__global__ void compact_k(const int* __restrict__ row, const int* __restrict__ col,
                          const int* __restrict__ newid,
                          int* __restrict__ orow, int* __restrict__ ocol,
                          int* __restrict__ cnt_next, int* __restrict__ counter,
                          const int* __restrict__ boundPtr, int maxE) {
    int e = blockIdx.x * blockDim.x + threadIdx.x;
    int bound = boundPtr ? __ldg(boundPtr) : maxE;
    bool valid = (e < bound);
    int nr = -1, nc = -1;
    if (valid) {
        nr = newid[row[e]];
        nc = newid[col[e]];
        valid = (nr >= 0) && (nc >= 0);
    }
    unsigned m = __ballot_sync(0xffffffffu, valid);
    if (valid) {
        int lane = threadIdx.x & 31;
        int leader = __ffs(m) - 1;
        int prefix = __popc(m & ((1u << lane) - 1u));
        int basep = 0;
        if (lane == leader) basep = atomicAdd(counter, __popc(m));
        basep = __shfl_sync(m, basep, leader);
        int pos = basep + prefix;
        orow[pos] = nr;
        ocol[pos] = nc;
        atomicAdd(&cnt_next[nc], 1);
    }
}

// ------------------------------- driver ------------------------------------
static inline int ceil_div(int a, int b) { return (a + b - 1) / b; }

struct Scratch {
    float *h, *cv, *xs1, *xs2, *xs3, *dinv, *sc, *pinv, *bf;
    int *nid, *cnt, *start, *cursor, *src, *r0, *c0, *r1, *c1, *nE;
    unsigned long long *ts;
};

extern "C" void kernel_launch(void* const* d_in, const int* in_sizes, int n_in,
                              void* d_out, int out_size)
{
    const float* x    = (const float*)d_in[0];
    const int*   erow = (const int*)  d_in[1];
    const int*   ecol = (const int*)  d_in[2];
    const float* W1 = (const float*)d_in[3],  *b1 = (const float*)d_in[4],  *p1 = (const float*)d_in[5];
    const float* W2 = (const float*)d_in[6],  *b2 = (const float*)d_in[7],  *p2 = (const float*)d_in[8];
    const float* W3 = (const float*)d_in[9],  *b3 = (const float*)d_in[10], *p3 = (const float*)d_in[11];
    float* out = (float*)d_out;
    const int E = in_sizes[1];

    Scratch S;
    cudaGetSymbolAddress((void**)&S.h,      g_h);
    cudaGetSymbolAddress((void**)&S.cv,     g_cv);
    cudaGetSymbolAddress((void**)&S.xs1,    g_xs1);
    cudaGetSymbolAddress((void**)&S.xs2,    g_xs2);
    cudaGetSymbolAddress((void**)&S.xs3,    g_xs3);
    cudaGetSymbolAddress((void**)&S.bf,     g_bf);
    cudaGetSymbolAddress((void**)&S.dinv,   g_dinv);
    cudaGetSymbolAddress((void**)&S.sc,     g_sc);
    cudaGetSymbolAddress((void**)&S.pinv,   g_pinv);
    cudaGetSymbolAddress((void**)&S.nid,    g_newid);
    cudaGetSymbolAddress((void**)&S.cnt,    g_cnt);
    cudaGetSymbolAddress((void**)&S.start,  g_start);
    cudaGetSymbolAddress((void**)&S.cursor, g_cursor);
    cudaGetSymbolAddress((void**)&S.ts,     g_tstate);
    cudaGetSymbolAddress((void**)&S.src,    g_src);
    cudaGetSymbolAddress((void**)&S.r0,     g_r0);
    cudaGetSymbolAddress((void**)&S.c0,     g_c0);
    cudaGetSymbolAddress((void**)&S.r1,     g_r1);
    cudaGetSymbolAddress((void**)&S.c1,     g_c1);
    cudaGetSymbolAddress((void**)&S.nE,     g_nE);

    // side stream + fork/join events, created once on the first (uncaptured)
    // correctness call; reused identically on every call thereafter.
    static cudaStream_t sB = nullptr;
    static cudaEvent_t evF[3], evJ[3];
    if (sB == nullptr) {
        cudaStreamCreateWithFlags(&sB, cudaStreamNonBlocking);
        for (int i = 0; i < 3; i++) {
            cudaEventCreateWithFlags(&evF[i], cudaEventDisableTiming);
            cudaEventCreateWithFlags(&evJ[i], cudaEventDisableTiming);
        }
    }

    // ---------------- Layer 1: n=131072, keep 512/1024 ----------------
    wsplit_k<<<779, 128>>>(W1, W2, W3, p1, p2, p3, S.bf, S.cnt, S.cursor, S.ts);
    cudaEventRecord(evF[0], 0);
    cudaStreamWaitEvent(sB, evF[0], 0);
    gemm_mma<<<NN1 / 128, 256, 0, sB>>>(x, S.bf, S.h);              // ∥ edge chain
    hist_k<<<ceil_div(E, 256), 256>>>(ecol, S.cnt, E);
    scan_k<<<NN1 / 1024, 1024>>>(S.cnt, S.start, S.dinv, S.ts);
    fill_k<<<ceil_div(E, 256), 256>>>(erow, ecol, S.start, S.cursor, S.src,
                                      nullptr, E);
    cudaEventRecord(evJ[0], sB);
    cudaStreamWaitEvent(0, evJ[0], 0);
    gather_k<<<ceil_div(NN1 * 32, 256), 256>>>(S.h, S.start, S.cnt, S.src,
                                               S.dinv, b1, p1, S.pinv + 0,
                                               S.cv, S.sc, NN1);
    topk_k<<<Bg, 1024>>>(S.cv, S.sc, S.xs1, S.nid, 1024, 512, out, 0,
                         S.cnt, S.cursor, S.nE + 0, NN2);
    compact_k<<<ceil_div(E, 256), 256>>>(erow, ecol, S.nid, S.r0, S.c0,
                                         S.cnt, S.nE + 0, nullptr, E);

    // ---------------- Layer 2: n=65536, keep 256/512 ----------------
    cudaEventRecord(evF[1], 0);
    cudaStreamWaitEvent(sB, evF[1], 0);
    gemm_mma<<<NN2 / 128, 256, 0, sB>>>(S.xs1, S.bf + 32768, S.h);  // ∥ edge chain
    scan_k<<<NN2 / 1024, 1024>>>(S.cnt, S.start, S.dinv, S.ts + 128);
    fill_k<<<ceil_div(E, 256), 256>>>(S.r0, S.c0, S.start, S.cursor, S.src,
                                      S.nE + 0, E);
    cudaEventRecord(evJ[1], sB);
    cudaStreamWaitEvent(0, evJ[1], 0);
    gather_k<<<ceil_div(NN2 * 32, 256), 256>>>(S.h, S.start, S.cnt, S.src,
                                               S.dinv, b2, p2, S.pinv + 1,
                                               S.cv, S.sc, NN2);
    topk_k<<<Bg, 512>>>(S.cv, S.sc, S.xs2, S.nid, 512, 256, out, 1,
                        S.cnt, S.cursor, S.nE + 1, NN3);
    compact_k<<<ceil_div(E, 256), 256>>>(S.r0, S.c0, S.nid, S.r1, S.c1,
                                         S.cnt, S.nE + 1, S.nE + 0, E);

    // ---------------- Layer 3: n=32768, keep 128/256 ----------------
    cudaEventRecord(evF[2], 0);
    cudaStreamWaitEvent(sB, evF[2], 0);
    gemm_mma<<<NN3 / 128, 256, 0, sB>>>(S.xs2, S.bf + 65536, S.h);  // ∥ edge chain
    scan_k<<<NN3 / 1024, 1024>>>(S.cnt, S.start, S.dinv, S.ts + 256);
    fill_k<<<ceil_div(E, 256), 256>>>(S.r1, S.c1, S.start, S.cursor, S.src,
                                      S.nE + 1, E);
    cudaEventRecord(evJ[2], sB);
    cudaStreamWaitEvent(0, evJ[2], 0);
    gather_k<<<ceil_div(NN3 * 32, 256), 256>>>(S.h, S.start, S.cnt, S.src,
                                               S.dinv, b3, p3, S.pinv + 2,
                                               S.cv, S.sc, NN3);
    topk_k<<<Bg, 256>>>(S.cv, S.sc, S.xs3, S.nid, 256, 128, out, 1,
                        nullptr, nullptr, nullptr, 0);
}